// round 1
// baseline (speedup 1.0000x reference)
#include <cuda_runtime.h>

#define NB 8
#define NX 256
#define NC 256

// Scratch: fused features and per-batch Gram matrices (no allocations allowed).
__device__ float g_f[NB * NX * NC];   // 2 MB
__device__ float g_G[NB * NC * NC];   // 2 MB

// ---------------------------------------------------------------------------
// K1: f[b,x,c] = wa*amp + wp*ph
// ---------------------------------------------------------------------------
__global__ void k_fuse(const float* __restrict__ amp, const float* __restrict__ ph,
                       const float* __restrict__ wa_p, const float* __restrict__ wp_p) {
    int i = blockIdx.x * blockDim.x + threadIdx.x;
    float wa = wa_p[0], wp = wp_p[0];
    g_f[i] = wa * amp[i] + wp * ph[i];
}

// ---------------------------------------------------------------------------
// K2: G[b] = f[b]^T f[b]  (per-batch 256x256x256 SGEMM)
// 64x64 block tile, 4x4 micro-tile, K-chunk 16, float4 shared loads.
// ---------------------------------------------------------------------------
__global__ __launch_bounds__(256) void k_gram() {
    __shared__ __align__(16) float As[16][64];
    __shared__ __align__(16) float Bs[16][64];

    int b = blockIdx.z;
    int cBase = blockIdx.y * 64;
    int dBase = blockIdx.x * 64;
    int tid = threadIdx.x;
    int tx = tid & 15;        // micro-tile col group (x4)
    int ty = tid >> 4;        // micro-tile row group (x4)

    const float* fb = g_f + b * NX * NC;

    float acc[4][4];
#pragma unroll
    for (int i = 0; i < 4; i++)
#pragma unroll
        for (int j = 0; j < 4; j++) acc[i][j] = 0.f;

    for (int k0 = 0; k0 < NX; k0 += 16) {
#pragma unroll
        for (int l = 0; l < 4; l++) {
            int idx = tid + l * 256;
            int r = idx >> 6;
            int col = idx & 63;
            As[r][col] = fb[(k0 + r) * NC + cBase + col];
            Bs[r][col] = fb[(k0 + r) * NC + dBase + col];
        }
        __syncthreads();

#pragma unroll
        for (int k = 0; k < 16; k++) {
            float4 a = *reinterpret_cast<const float4*>(&As[k][ty << 2]);
            float4 v = *reinterpret_cast<const float4*>(&Bs[k][tx << 2]);
            float av[4] = {a.x, a.y, a.z, a.w};
            float bv[4] = {v.x, v.y, v.z, v.w};
#pragma unroll
            for (int i = 0; i < 4; i++)
#pragma unroll
                for (int j = 0; j < 4; j++) acc[i][j] += av[i] * bv[j];
        }
        __syncthreads();
    }

    float* Gout = g_G + b * NC * NC;
#pragma unroll
    for (int i = 0; i < 4; i++) {
        int c = cBase + (ty << 2) + i;
        float4 st = make_float4(acc[i][0], acc[i][1], acc[i][2], acc[i][3]);
        *reinterpret_cast<float4*>(&Gout[c * NC + dBase + (tx << 2)]) = st;
    }
}

// ---------------------------------------------------------------------------
// K3: zero output (poisoned by harness)
// ---------------------------------------------------------------------------
__global__ void k_zero(float* __restrict__ out) {
    out[blockIdx.x * blockDim.x + threadIdx.x] = 0.f;
}

// ---------------------------------------------------------------------------
// K4: per (b,c) row: dist -> exp_dist -> row max -> p -> logit -> gumbel
//     hard sample; accumulate mean over b via atomicAdd of exact 1/8ths.
// ---------------------------------------------------------------------------
__global__ __launch_bounds__(256) void k_mask(const float* __restrict__ A,
                                              const float* __restrict__ gu,
                                              float* __restrict__ out) {
    int bc = blockIdx.x;          // b*NC + c
    int b = bc >> 8;
    int c = bc & 255;
    int d = threadIdx.x;

    const float* Gb = g_G + b * NC * NC;
    float Gv = Gb[c * NC + d];
    float Sc = Gb[c * NC + c];
    float Sd = Gb[d * NC + d];
    float Ad = A[d * NC + d];

    float dist = (Ad * Ad) * (Sc + Sd - 2.f * Gv);
    float e = 1.f / (dist + 1e-10f);
    if (d == c) e = 0.f;

    // block max-reduce over d
    float m = e;
#pragma unroll
    for (int o = 16; o > 0; o >>= 1)
        m = fmaxf(m, __shfl_xor_sync(0xffffffffu, m, o));
    __shared__ float warpmax[8];
    if ((threadIdx.x & 31) == 0) warpmax[threadIdx.x >> 5] = m;
    __syncthreads();
    float emax = warpmax[0];
#pragma unroll
    for (int w = 1; w < 8; w++) emax = fmaxf(emax, warpmax[w]);

    float p = (d == c) ? 0.99f : 0.99f * (e / emax);
    float logit = logf(p / (1.f - p));

    const float* g2 = gu + ((size_t)bc * NC + d) * 2;
    float u0 = g2[0];
    float u1 = g2[1];
    float g0 = -logf(-logf(u0));
    float g1 = -logf(-logf(u1));

    // hard0 = (y0 > y1)  <=>  logit + g0 > -logit + g1
    if (logit + g0 > -logit + g1)
        atomicAdd(&out[c * NC + d], 0.125f);
}

// ---------------------------------------------------------------------------
extern "C" void kernel_launch(void* const* d_in, const int* in_sizes, int n_in,
                              void* d_out, int out_size) {
    const float* amp = (const float*)d_in[0];
    const float* ph  = (const float*)d_in[1];
    const float* A   = (const float*)d_in[2];
    const float* wa  = (const float*)d_in[3];
    const float* wp  = (const float*)d_in[4];
    const float* gu  = (const float*)d_in[5];
    float* out = (float*)d_out;

    k_fuse<<<(NB * NX * NC) / 256, 256>>>(amp, ph, wa, wp);
    k_gram<<<dim3(4, 4, 8), 256>>>();
    k_zero<<<(NC * NC) / 256, 256>>>(out);
    k_mask<<<NB * NC, 256>>>(A, gu, out);
}

// round 3
// speedup vs baseline: 1.0844x; 1.0844x over previous
#include <cuda_runtime.h>

#define NB 8
#define NX 256
#define NC 256
#define KSEG 4
#define KLEN 64   /* NX / KSEG */
#define KC 8      /* smem chunk depth */

typedef unsigned long long u64;

// Split-K partial Gram matrices: [seg][b][c*NC+d]  (8 MB)
__device__ float g_G[KSEG * NB * NC * NC];
// Diagonal partials: [seg][b][c]  (32 KB)
__device__ float g_Sp[KSEG * NB * NC];

__device__ __forceinline__ u64 ffma2(u64 a, u64 b, u64 c) {
    u64 d;
    asm("fma.rn.f32x2 %0, %1, %2, %3;" : "=l"(d) : "l"(a), "l"(b), "l"(c));
    return d;
}
__device__ __forceinline__ u64 pack2(float x) {
    u64 d;
    unsigned xi = __float_as_uint(x);
    asm("mov.b64 %0, {%1, %1};" : "=l"(d) : "r"(xi));
    return d;
}

// ---------------------------------------------------------------------------
// K1: partial Gram  G[seg][b] += f[:,c]^T f[:,d] over k in [seg*64, seg*64+64)
//     f computed on the fly from amp/ph (k_fuse fused into staging).
//     128x128 tile, 8x8 micro-tile with packed f32x2 FMAs.
//     grid = (16, 8): blockIdx.x = seg*4 + quad, blockIdx.y = b
// ---------------------------------------------------------------------------
__global__ __launch_bounds__(256) void k_gram(const float* __restrict__ amp,
                                              const float* __restrict__ ph,
                                              const float* __restrict__ wap,
                                              const float* __restrict__ wpp) {
    __shared__ __align__(16) float As[KC][128];
    __shared__ __align__(16) float Bs[KC][128];

    int b = blockIdx.y;
    int q = blockIdx.x & 3;
    int seg = blockIdx.x >> 2;
    int cBase = (q >> 1) * 128;
    int dBase = (q & 1) * 128;
    int tid = threadIdx.x;
    int tx = tid & 15;       // 16 col groups x 8 cols
    int ty = tid >> 4;       // 16 row groups x 8 rows
    int sr = tid >> 5;       // staging row 0..7
    int sc = (tid & 31) * 4; // staging col 0..124

    float wa = wap[0], wp = wpp[0];
    const float* ab = amp + b * NX * NC;
    const float* pb = ph + b * NX * NC;

    u64 acc[8][4];
#pragma unroll
    for (int i = 0; i < 8; i++)
#pragma unroll
        for (int j = 0; j < 4; j++) acc[i][j] = 0ull;

    int k0 = seg * KLEN;

    // prologue: load chunk 0 into registers
    float4 ra, rp, rb, rq;
    {
        int krow = k0 + sr;
        ra = *(const float4*)(ab + krow * NC + cBase + sc);
        rp = *(const float4*)(pb + krow * NC + cBase + sc);
        rb = *(const float4*)(ab + krow * NC + dBase + sc);
        rq = *(const float4*)(pb + krow * NC + dBase + sc);
    }

    for (int ch = 0; ch < KLEN / KC; ch++) {
        __syncthreads();
        float4 fa = make_float4(wa * ra.x + wp * rp.x, wa * ra.y + wp * rp.y,
                                wa * ra.z + wp * rp.z, wa * ra.w + wp * rp.w);
        float4 fb = make_float4(wa * rb.x + wp * rq.x, wa * rb.y + wp * rq.y,
                                wa * rb.z + wp * rq.z, wa * rb.w + wp * rq.w);
        *(float4*)&As[sr][sc] = fa;
        *(float4*)&Bs[sr][sc] = fb;
        __syncthreads();

        if (ch + 1 < KLEN / KC) {
            int krow = k0 + (ch + 1) * KC + sr;
            ra = *(const float4*)(ab + krow * NC + cBase + sc);
            rp = *(const float4*)(pb + krow * NC + cBase + sc);
            rb = *(const float4*)(ab + krow * NC + dBase + sc);
            rq = *(const float4*)(pb + krow * NC + dBase + sc);
        }

#pragma unroll
        for (int k = 0; k < KC; k++) {
            float4 a0 = *(const float4*)&As[k][ty * 8];
            float4 a1 = *(const float4*)&As[k][ty * 8 + 4];
            const u64* brow = (const u64*)&Bs[k][tx * 8];
            u64 b2[4];
            b2[0] = brow[0]; b2[1] = brow[1]; b2[2] = brow[2]; b2[3] = brow[3];
            float av[8] = {a0.x, a0.y, a0.z, a0.w, a1.x, a1.y, a1.z, a1.w};
#pragma unroll
            for (int i = 0; i < 8; i++) {
                u64 ai = pack2(av[i]);
#pragma unroll
                for (int j = 0; j < 4; j++) acc[i][j] = ffma2(ai, b2[j], acc[i][j]);
            }
        }
    }

    // store partial G tile
    float* Gp = g_G + (size_t)(seg * NB + b) * NC * NC;
#pragma unroll
    for (int i = 0; i < 8; i++) {
        int c = cBase + ty * 8 + i;
        u64* dst = (u64*)(Gp + c * NC + dBase + tx * 8);
        dst[0] = acc[i][0]; dst[1] = acc[i][1]; dst[2] = acc[i][2]; dst[3] = acc[i][3];
    }

    // diagonal partials (only diag quads; only threads whose micro-tile hits diag)
    if (cBase == dBase && tx == ty) {
        float* Sp = g_Sp + (seg * NB + b) * NC;
#pragma unroll
        for (int i = 0; i < 8; i++) {
            int c = cBase + ty * 8 + i;
            u64 v = acc[i][i >> 1];
            float f = (i & 1) ? __uint_as_float((unsigned)(v >> 32))
                              : __uint_as_float((unsigned)(v & 0xffffffffu));
            Sp[c] = f;
        }
    }
}

// ---------------------------------------------------------------------------
// K2: per c (block) x d (thread), loop over b:
//     D = Ad^2*(Sc+Sd-2G)+1e-10 ; Dmin = min_{d!=c} D ; r = .99 Dmin/(D-.99 Dmin)
//     sample: r^2 * (-ln u1) > (-ln u0)  -> count ; out = count/8
// ---------------------------------------------------------------------------
__global__ __launch_bounds__(256) void k_mask(const float* __restrict__ A,
                                              const float* __restrict__ gu,
                                              float* __restrict__ out) {
    int c = blockIdx.x;
    int d = threadIdx.x;
    __shared__ float red[8];
    __shared__ float scs;

    float Ad = A[d * (NC + 1)];
    float Ad2 = Ad * Ad;
    const float RDIAG = 0.99f / (1.0f - 0.99f);

    int cnt = 0;
#pragma unroll 1
    for (int b = 0; b < NB; b++) {
        float Gv = 0.f, Sd = 0.f;
#pragma unroll
        for (int s = 0; s < KSEG; s++) {
            Gv += g_G[(size_t)(s * NB + b) * NC * NC + c * NC + d];
            Sd += g_Sp[(s * NB + b) * NC + d];
        }
        if (d == c) scs = Sd;
        __syncthreads();
        float Sc = scs;

        float D = Ad2 * (Sc + Sd - 2.f * Gv) + 1e-10f;
        float m = (d == c) ? __int_as_float(0x7f800000) : D;
#pragma unroll
        for (int o = 16; o > 0; o >>= 1)
            m = fminf(m, __shfl_xor_sync(0xffffffffu, m, o));
        if ((d & 31) == 0) red[d >> 5] = m;
        __syncthreads();
        float Dmin = fminf(fminf(fminf(red[0], red[1]), fminf(red[2], red[3])),
                           fminf(fminf(red[4], red[5]), fminf(red[6], red[7])));

        float r;
        if (d == c) {
            r = RDIAG;
        } else {
            float num = 0.99f * Dmin;
            r = num / (D - num);
        }

        float2 u = *(const float2*)(gu + (size_t)((b * NC + c) * NC + d) * 2);
        float lu0 = -logf(u.x);
        float lu1 = -logf(u.y);
        if (r * r * lu1 > lu0) cnt++;
    }
    out[c * NC + d] = (float)cnt * 0.125f;
}

// ---------------------------------------------------------------------------
extern "C" void kernel_launch(void* const* d_in, const int* in_sizes, int n_in,
                              void* d_out, int out_size) {
    const float* amp = (const float*)d_in[0];
    const float* ph  = (const float*)d_in[1];
    const float* A   = (const float*)d_in[2];
    const float* wa  = (const float*)d_in[3];
    const float* wp  = (const float*)d_in[4];
    const float* gu  = (const float*)d_in[5];
    float* out = (float*)d_out;

    k_gram<<<dim3(16, NB), 256>>>(amp, ph, wa, wp);
    k_mask<<<NC, 256>>>(A, gu, out);
}

// round 8
// speedup vs baseline: 1.2398x; 1.1433x over previous
#include <cuda_runtime.h>

#define NB 8
#define NX 256
#define NC 256
#define KSEG 4
#define KLEN 64   /* NX / KSEG */
#define KC 8      /* smem chunk depth */

typedef unsigned long long u64;

// Split-K partial Gram matrices: [seg][b][c*NC+d]  (8 MB)
__device__ float g_G[KSEG * NB * NC * NC];
// Diagonal partials: [seg][b][c]  (32 KB)
__device__ float g_Sp[KSEG * NB * NC];

__device__ __forceinline__ u64 ffma2(u64 a, u64 b, u64 c) {
    u64 d;
    asm("fma.rn.f32x2 %0, %1, %2, %3;" : "=l"(d) : "l"(a), "l"(b), "l"(c));
    return d;
}
__device__ __forceinline__ u64 pack2(float x) {
    u64 d;
    unsigned xi = __float_as_uint(x);
    asm("mov.b64 %0, {%1, %1};" : "=l"(d) : "r"(xi));
    return d;
}

// ---------------------------------------------------------------------------
// K1: partial Gram  G[seg][b] += f[:,c]^T f[:,d] over k in [seg*64, seg*64+64)
//     f computed on the fly from amp/ph. 128x128 tile, 8x8 micro-tile,
//     packed f32x2 FMAs. grid = (16, 8): blockIdx.x = seg*4+quad, .y = b
// ---------------------------------------------------------------------------
__global__ __launch_bounds__(256) void k_gram(const float* __restrict__ amp,
                                              const float* __restrict__ ph,
                                              const float* __restrict__ wap,
                                              const float* __restrict__ wpp) {
    __shared__ __align__(16) float As[KC][128];
    __shared__ __align__(16) float Bs[KC][128];

    int b = blockIdx.y;
    int q = blockIdx.x & 3;
    int seg = blockIdx.x >> 2;
    int cBase = (q >> 1) * 128;
    int dBase = (q & 1) * 128;
    int tid = threadIdx.x;
    int tx = tid & 15;       // 16 col groups x 8 cols
    int ty = tid >> 4;       // 16 row groups x 8 rows
    int sr = tid >> 5;       // staging row 0..7
    int sc = (tid & 31) * 4; // staging col 0..124

    float wa = wap[0], wp = wpp[0];
    const float* ab = amp + b * NX * NC;
    const float* pb = ph + b * NX * NC;

    u64 acc[8][4];
#pragma unroll
    for (int i = 0; i < 8; i++)
#pragma unroll
        for (int j = 0; j < 4; j++) acc[i][j] = 0ull;

    int k0 = seg * KLEN;

    float4 ra, rp, rb, rq;
    {
        int krow = k0 + sr;
        ra = *(const float4*)(ab + krow * NC + cBase + sc);
        rp = *(const float4*)(pb + krow * NC + cBase + sc);
        rb = *(const float4*)(ab + krow * NC + dBase + sc);
        rq = *(const float4*)(pb + krow * NC + dBase + sc);
    }

    for (int ch = 0; ch < KLEN / KC; ch++) {
        __syncthreads();
        float4 fa = make_float4(wa * ra.x + wp * rp.x, wa * ra.y + wp * rp.y,
                                wa * ra.z + wp * rp.z, wa * ra.w + wp * rp.w);
        float4 fb = make_float4(wa * rb.x + wp * rq.x, wa * rb.y + wp * rq.y,
                                wa * rb.z + wp * rq.z, wa * rb.w + wp * rq.w);
        *(float4*)&As[sr][sc] = fa;
        *(float4*)&Bs[sr][sc] = fb;
        __syncthreads();

        if (ch + 1 < KLEN / KC) {
            int krow = k0 + (ch + 1) * KC + sr;
            ra = *(const float4*)(ab + krow * NC + cBase + sc);
            rp = *(const float4*)(pb + krow * NC + cBase + sc);
            rb = *(const float4*)(ab + krow * NC + dBase + sc);
            rq = *(const float4*)(pb + krow * NC + dBase + sc);
        }

#pragma unroll
        for (int k = 0; k < KC; k++) {
            float4 a0 = *(const float4*)&As[k][ty * 8];
            float4 a1 = *(const float4*)&As[k][ty * 8 + 4];
            const u64* brow = (const u64*)&Bs[k][tx * 8];
            u64 b2[4];
            b2[0] = brow[0]; b2[1] = brow[1]; b2[2] = brow[2]; b2[3] = brow[3];
            float av[8] = {a0.x, a0.y, a0.z, a0.w, a1.x, a1.y, a1.z, a1.w};
#pragma unroll
            for (int i = 0; i < 8; i++) {
                u64 ai = pack2(av[i]);
#pragma unroll
                for (int j = 0; j < 4; j++) acc[i][j] = ffma2(ai, b2[j], acc[i][j]);
            }
        }
    }

    float* Gp = g_G + (size_t)(seg * NB + b) * NC * NC;
#pragma unroll
    for (int i = 0; i < 8; i++) {
        int c = cBase + ty * 8 + i;
        u64* dst = (u64*)(Gp + c * NC + dBase + tx * 8);
        dst[0] = acc[i][0]; dst[1] = acc[i][1]; dst[2] = acc[i][2]; dst[3] = acc[i][3];
    }

    if (cBase == dBase && tx == ty) {
        float* Sp = g_Sp + (seg * NB + b) * NC;
#pragma unroll
        for (int i = 0; i < 8; i++) {
            int c = cBase + ty * 8 + i;
            u64 v = acc[i][i >> 1];
            float f = (i & 1) ? __uint_as_float((unsigned)(v >> 32))
                              : __uint_as_float((unsigned)(v & 0xffffffffu));
            Sp[c] = f;
        }
    }
}

// ---------------------------------------------------------------------------
// K2: grid = c (256), block = 1024 = (d:256) x (bq:4); each thread does
//     b = bq and b = bq+4. Per b: D = Ad^2*(Sc+Sd-2G)+1e-10,
//     Dmin = min_{d!=c} D, r = .99*Dmin/(D-.99*Dmin), sample:
//     r^2*(-ln u1) > -ln u0. Sum over b in smem -> single store, no atomics.
// ---------------------------------------------------------------------------
__global__ __launch_bounds__(1024) void k_mask(const float* __restrict__ A,
                                               const float* __restrict__ gu,
                                               float* __restrict__ out) {
    int c = blockIdx.x;
    int tid = threadIdx.x;
    int d = tid & 255;
    int bq = tid >> 8;           // 0..3
    __shared__ float red[4][8];
    __shared__ int s_cnt[4][256];

    float Ad = A[d * (NC + 1)];
    float Ad2 = Ad * Ad;
    const float RDIAG = 0.99f / (1.0f - 0.99f);

    int cnt = 0;
#pragma unroll
    for (int it = 0; it < 2; it++) {
        int b = bq + it * 4;

        float Gv = 0.f, Sd = 0.f, Sc = 0.f;
#pragma unroll
        for (int s = 0; s < KSEG; s++) {
            Gv += g_G[(size_t)(s * NB + b) * NC * NC + c * NC + d];
            Sd += g_Sp[(s * NB + b) * NC + d];
            Sc += g_Sp[(s * NB + b) * NC + c];
        }

        float D = Ad2 * (Sc + Sd - 2.f * Gv) + 1e-10f;
        float m = (d == c) ? __int_as_float(0x7f800000) : D;
#pragma unroll
        for (int o = 16; o > 0; o >>= 1)
            m = fminf(m, __shfl_xor_sync(0xffffffffu, m, o));
        if ((d & 31) == 0) red[bq][d >> 5] = m;
        __syncthreads();
        float Dmin = fminf(fminf(fminf(red[bq][0], red[bq][1]),
                                 fminf(red[bq][2], red[bq][3])),
                           fminf(fminf(red[bq][4], red[bq][5]),
                                 fminf(red[bq][6], red[bq][7])));

        float r;
        if (d == c) {
            r = RDIAG;
        } else {
            float num = 0.99f * Dmin;
            r = num / (D - num);
        }

        float2 u = *(const float2*)(gu + (size_t)((b * NC + c) * NC + d) * 2);
        float lu0 = -logf(u.x);
        float lu1 = -logf(u.y);
        if (r * r * lu1 > lu0) cnt++;
        __syncthreads();   // red[] reused next iteration
    }

    s_cnt[bq][d] = cnt;
    __syncthreads();
    if (bq == 0) {
        int tot = s_cnt[0][d] + s_cnt[1][d] + s_cnt[2][d] + s_cnt[3][d];
        out[c * NC + d] = (float)tot * 0.125f;
    }
}

// ---------------------------------------------------------------------------
extern "C" void kernel_launch(void* const* d_in, const int* in_sizes, int n_in,
                              void* d_out, int out_size) {
    const float* amp = (const float*)d_in[0];
    const float* ph  = (const float*)d_in[1];
    const float* A   = (const float*)d_in[2];
    const float* wa  = (const float*)d_in[3];
    const float* wp  = (const float*)d_in[4];
    const float* gu  = (const float*)d_in[5];
    float* out = (float*)d_out;

    k_gram<<<dim3(16, NB), 256>>>(amp, ph, wa, wp);
    k_mask<<<NC, 1024>>>(A, gu, out);
}